// round 16
// baseline (speedup 1.0000x reference)
#include <cuda_runtime.h>
#include <cuda_bf16.h>

#define NUM_GRAPHS 2048
#define D 128
#define EPS 1e-6f
#define NW 16          // warps per block
#define NT (NW * 32)   // 512 threads

// 256-bit first-touch load with evict_last (the exact form ptxas requires:
// ".L2::evict_last" is only legal with .v8.b32 / .v4.b64)
static __device__ __forceinline__ void ldg_keep8(const float* p, float4& lo, float4& hi) {
    unsigned a0, a1, a2, a3, a4, a5, a6, a7;
    asm volatile("ld.global.nc.L2::evict_last.v8.b32 {%0,%1,%2,%3,%4,%5,%6,%7}, [%8];"
                 : "=r"(a0), "=r"(a1), "=r"(a2), "=r"(a3),
                   "=r"(a4), "=r"(a5), "=r"(a6), "=r"(a7)
                 : "l"(p));
    lo.x = __uint_as_float(a0); lo.y = __uint_as_float(a1);
    lo.z = __uint_as_float(a2); lo.w = __uint_as_float(a3);
    hi.x = __uint_as_float(a4); hi.y = __uint_as_float(a5);
    hi.z = __uint_as_float(a6); hi.w = __uint_as_float(a7);
}

static __device__ __forceinline__ void acc8(const float4& lo, const float4& hi,
                                            float4& slo, float4& shi,
                                            float4& qlo, float4& qhi) {
    slo.x += lo.x; slo.y += lo.y; slo.z += lo.z; slo.w += lo.w;
    shi.x += hi.x; shi.y += hi.y; shi.z += hi.z; shi.w += hi.w;
    qlo.x += lo.x * lo.x; qlo.y += lo.y * lo.y; qlo.z += lo.z * lo.z; qlo.w += lo.w * lo.w;
    qhi.x += hi.x * hi.x; qhi.y += hi.y * hi.y; qhi.z += hi.z * hi.z; qhi.w += hi.w * hi.w;
}

// first index i in [0,n) with ids[i*mul] >= v  (ids sorted ascending)
static __device__ __forceinline__ int lower_bound_ids(const int* __restrict__ ids32,
                                                      int n, int mul, int v) {
    int lo = 0, hi = n;
    while (lo < hi) {
        int mid = (lo + hi) >> 1;
        if (ids32[(long long)mid * mul] < v) lo = mid + 1; else hi = mid;
    }
    return lo;
}

// ---------------- single fused kernel: bounds + moments + normalize ----------------
// One block per segment, 512 threads. Threads 0/1 binary-search the block's row
// range [s,e) in the sorted ids (dtype probed from ids32[n-1]: int64 LE high word
// is 0). Thread owns 8 contiguous columns (lane8 = tid&15); "part" = tid>>4 in
// [0,32) selects its row stream. Pass A: 256-bit evict_last loads; pass B:
// streaming __ldcs/__stcs with stats broadcast through smem.
__global__ void __launch_bounds__(NT, 2) graphnorm_fused_kernel(
    const float* __restrict__ feat,
    const int*   __restrict__ ids32,
    const float* __restrict__ weight,
    const float* __restrict__ bias,
    const float* __restrict__ mean_scale,
    float* __restrict__ out,
    int n)
{
    __shared__ float4 s_lo[32][16];   // per-part partial sums, low 4 cols
    __shared__ float4 s_hi[32][16];   // high 4 cols
    __shared__ float4 q_lo[32][16];   // partial sumsq
    __shared__ float4 q_hi[32][16];
    __shared__ float4 s_mm[32];       // [lane8] = lo, [lane8+16] = hi
    __shared__ float4 s_wd[32];
    __shared__ int    s_bounds[2];    // [0]=s, [1]=e

    const int seg   = blockIdx.x;
    const int lane8 = threadIdx.x & 15;   // column group (8 cols)
    const int part  = threadIdx.x >> 4;   // 0..31: row stream

    // ---- inline boundary search (replaces the separate seg_bounds kernel) ----
    if (threadIdx.x < 2) {
        const int mul = (n > 1 && ids32[n - 1] == 0) ? 2 : 1;  // int64 LE probe
        s_bounds[threadIdx.x] = lower_bound_ids(ids32, n, mul, seg + threadIdx.x);
    }
    __syncthreads();
    const int s   = s_bounds[0];
    const int e   = s_bounds[1];
    const int cnt = e - s;

    if (cnt <= 0) return;   // block-uniform: barrier-safe

    const float* base = feat + (long long)s * D + lane8 * 8;

    float4 slo = make_float4(0.f, 0.f, 0.f, 0.f), shi = slo, qlo = slo, qhi = slo;

    // ---- pass A: moments (unroll-2, row stride 32) ----
    int r = part;
    for (; r + 32 < cnt; r += 64) {
        float4 l0, h0, l1, h1;
        ldg_keep8(base + (long long)r * D, l0, h0);
        ldg_keep8(base + (long long)(r + 32) * D, l1, h1);
        acc8(l0, h0, slo, shi, qlo, qhi);
        acc8(l1, h1, slo, shi, qlo, qhi);
    }
    if (r < cnt) {
        float4 l0, h0;
        ldg_keep8(base + (long long)r * D, l0, h0);
        acc8(l0, h0, slo, shi, qlo, qhi);
    }

    s_lo[part][lane8] = slo;  s_hi[part][lane8] = shi;
    q_lo[part][lane8] = qlo;  q_hi[part][lane8] = qhi;
    __syncthreads();

    // ---- reduce + finalize (threads 0-15: lo halves, 16-31: hi halves) ----
    if (threadIdx.x < 32) {
        const int  l  = threadIdx.x & 15;
        const bool hi = threadIdx.x >= 16;
        float4 ts = make_float4(0.f, 0.f, 0.f, 0.f), tq = ts;
        #pragma unroll
        for (int w = 0; w < 32; ++w) {
            float4 a = hi ? s_hi[w][l] : s_lo[w][l];
            float4 b = hi ? q_hi[w][l] : q_lo[w][l];
            ts.x += a.x; ts.y += a.y; ts.z += a.z; ts.w += a.w;
            tq.x += b.x; tq.y += b.y; tq.z += b.z; tq.w += b.w;
        }
        const float inv = 1.f / (float)cnt;
        float4 msv = ((const float4*)mean_scale)[l * 2 + (hi ? 1 : 0)];
        float4 wv  = ((const float4*)weight)[l * 2 + (hi ? 1 : 0)];
        float4 mm, wd;
        float mean, v;
        mean = ts.x * inv; mm.x = mean * msv.x;
        v = tq.x * inv - 2.f * mm.x * mean + mm.x * mm.x; wd.x = wv.x * rsqrtf(v + EPS);
        mean = ts.y * inv; mm.y = mean * msv.y;
        v = tq.y * inv - 2.f * mm.y * mean + mm.y * mm.y; wd.y = wv.y * rsqrtf(v + EPS);
        mean = ts.z * inv; mm.z = mean * msv.z;
        v = tq.z * inv - 2.f * mm.z * mean + mm.z * mm.z; wd.z = wv.z * rsqrtf(v + EPS);
        mean = ts.w * inv; mm.w = mean * msv.w;
        v = tq.w * inv - 2.f * mm.w * mean + mm.w * mm.w; wd.w = wv.w * rsqrtf(v + EPS);
        s_mm[threadIdx.x] = mm;
        s_wd[threadIdx.x] = wd;
    }
    __syncthreads();

    const float4 mmlo = s_mm[lane8],      mmhi = s_mm[lane8 + 16];
    const float4 wdlo = s_wd[lane8],      wdhi = s_wd[lane8 + 16];
    const float4 bvlo = ((const float4*)bias)[lane8 * 2];
    const float4 bvhi = ((const float4*)bias)[lane8 * 2 + 1];

    // ---- pass B: normalize + write (unroll-2, streaming) ----
    const float4* pf = (const float4*)(feat) + (long long)s * 32 + lane8 * 2;
    float4*       po = (float4*)(out)        + (long long)s * 32 + lane8 * 2;
    r = part;
    for (; r + 32 < cnt; r += 64) {
        float4 x0 = __ldcs(pf + (long long)r * 32);
        float4 y0 = __ldcs(pf + (long long)r * 32 + 1);
        float4 x1 = __ldcs(pf + (long long)(r + 32) * 32);
        float4 y1 = __ldcs(pf + (long long)(r + 32) * 32 + 1);
        float4 a, b;
        a.x = fmaf(wdlo.x, x0.x - mmlo.x, bvlo.x); a.y = fmaf(wdlo.y, x0.y - mmlo.y, bvlo.y);
        a.z = fmaf(wdlo.z, x0.z - mmlo.z, bvlo.z); a.w = fmaf(wdlo.w, x0.w - mmlo.w, bvlo.w);
        b.x = fmaf(wdhi.x, y0.x - mmhi.x, bvhi.x); b.y = fmaf(wdhi.y, y0.y - mmhi.y, bvhi.y);
        b.z = fmaf(wdhi.z, y0.z - mmhi.z, bvhi.z); b.w = fmaf(wdhi.w, y0.w - mmhi.w, bvhi.w);
        __stcs(po + (long long)r * 32, a);
        __stcs(po + (long long)r * 32 + 1, b);
        a.x = fmaf(wdlo.x, x1.x - mmlo.x, bvlo.x); a.y = fmaf(wdlo.y, x1.y - mmlo.y, bvlo.y);
        a.z = fmaf(wdlo.z, x1.z - mmlo.z, bvlo.z); a.w = fmaf(wdlo.w, x1.w - mmlo.w, bvlo.w);
        b.x = fmaf(wdhi.x, y1.x - mmhi.x, bvhi.x); b.y = fmaf(wdhi.y, y1.y - mmhi.y, bvhi.y);
        b.z = fmaf(wdhi.z, y1.z - mmhi.z, bvhi.z); b.w = fmaf(wdhi.w, y1.w - mmhi.w, bvhi.w);
        __stcs(po + (long long)(r + 32) * 32, a);
        __stcs(po + (long long)(r + 32) * 32 + 1, b);
    }
    if (r < cnt) {
        float4 x0 = __ldcs(pf + (long long)r * 32);
        float4 y0 = __ldcs(pf + (long long)r * 32 + 1);
        float4 a, b;
        a.x = fmaf(wdlo.x, x0.x - mmlo.x, bvlo.x); a.y = fmaf(wdlo.y, x0.y - mmlo.y, bvlo.y);
        a.z = fmaf(wdlo.z, x0.z - mmlo.z, bvlo.z); a.w = fmaf(wdlo.w, x0.w - mmlo.w, bvlo.w);
        b.x = fmaf(wdhi.x, y0.x - mmhi.x, bvhi.x); b.y = fmaf(wdhi.y, y0.y - mmhi.y, bvhi.y);
        b.z = fmaf(wdhi.z, y0.z - mmhi.z, bvhi.z); b.w = fmaf(wdhi.w, y0.w - mmhi.w, bvhi.w);
        __stcs(po + (long long)r * 32, a);
        __stcs(po + (long long)r * 32 + 1, b);
    }
}

extern "C" void kernel_launch(void* const* d_in, const int* in_sizes, int n_in,
                              void* d_out, int out_size) {
    const float* feat = (const float*)d_in[0];
    const int*   ids  = (const int*)d_in[1];   // int32 expected; int64 auto-detected
    const float* w    = (const float*)d_in[2];
    const float* b    = (const float*)d_in[3];
    const float* ms   = (const float*)d_in[4];
    float* out = (float*)d_out;
    const int n = in_sizes[1];  // number of nodes

    graphnorm_fused_kernel<<<NUM_GRAPHS, NT>>>(feat, ids, w, b, ms, out, n);
}